// round 1
// baseline (speedup 1.0000x reference)
#include <cuda_runtime.h>

// PLIF spiking neuron forward.
// x: [B=16, T=32, C=128, H=32, W=32] fp32
// a: scalar fp32 (decay = sigmoid(a))
// out: spikes, same shape as x, fp32 {0,1}
//
// Per (b,c,h,w) site: T=32 recurrence
//   mem = decay*mem + x[t];  s = (mem >= 1.0f);  mem = s ? 0 : mem;
//
// One thread handles 4 contiguous floats (float4) at a fixed (b, chw/4),
// looping over t with stride CHW. Fully coalesced, HBM-bound.

constexpr int B = 16;
constexpr int T = 32;
constexpr int C = 128;
constexpr int H = 32;
constexpr int W = 32;
constexpr int CHW_V4   = (C * H * W) / 4;   // 32768 float4 per (b,t) slice
constexpr int TOTAL_V4 = B * CHW_V4;        // 524288 float4 sites

__global__ __launch_bounds__(256)
void plif_fwd_kernel(const float4* __restrict__ x,
                     const float*  __restrict__ a,
                     float4*       __restrict__ out)
{
    int i = blockIdx.x * blockDim.x + threadIdx.x;
    if (i >= TOTAL_V4) return;

    int b   = i / CHW_V4;
    int chw = i - b * CHW_V4;
    int base = b * (T * CHW_V4) + chw;   // vec index of t=0 for this site

    // decay = sigmoid(a); computed once per thread, negligible cost.
    float av = __ldg(a);
    float decay = 1.0f / (1.0f + expf(-av));

    float mx = 0.0f, my = 0.0f, mz = 0.0f, mw = 0.0f;

    #pragma unroll 8
    for (int t = 0; t < T; t++) {
        float4 xi = __ldcs(&x[base + t * CHW_V4]);

        mx = fmaf(decay, mx, xi.x);
        my = fmaf(decay, my, xi.y);
        mz = fmaf(decay, mz, xi.z);
        mw = fmaf(decay, mw, xi.w);

        float4 s;
        s.x = (mx >= 1.0f) ? 1.0f : 0.0f;
        s.y = (my >= 1.0f) ? 1.0f : 0.0f;
        s.z = (mz >= 1.0f) ? 1.0f : 0.0f;
        s.w = (mw >= 1.0f) ? 1.0f : 0.0f;

        // hard reset
        mx = (mx >= 1.0f) ? 0.0f : mx;
        my = (my >= 1.0f) ? 0.0f : my;
        mz = (mz >= 1.0f) ? 0.0f : mz;
        mw = (mw >= 1.0f) ? 0.0f : mw;

        __stcs(&out[base + t * CHW_V4], s);
    }
}

extern "C" void kernel_launch(void* const* d_in, const int* in_sizes, int n_in,
                              void* d_out, int out_size)
{
    const float4* x  = (const float4*)d_in[0];
    const float*  a  = (const float*)d_in[1];
    float4*       out = (float4*)d_out;

    constexpr int THREADS = 256;
    constexpr int BLOCKS  = (TOTAL_V4 + THREADS - 1) / THREADS;  // 2048

    plif_fwd_kernel<<<BLOCKS, THREADS>>>(x, a, out);
}